// round 13
// baseline (speedup 1.0000x reference)
#include <cuda_runtime.h>
#include <cuda_fp16.h>
#include <cstdint>

// ============================================================================
// Reduction: softmax over length-1 key axis == 1  =>  attended = V-projection.
//   a1 = LN( v2 @ (Wo1@Wv2)^T + (Wo1@bv2 + bo1) + v1 ; g1, be1 )
//   a2 = LN( v1 @ (Wo2@Wv1)^T + (Wo2@bv1 + bo2) + v2 ; g2, be2 )
//
// R4: column permutation P -> fragment-contiguous layouts (LDG.128/STG.128).
// R6: persistent CTAs (304), per-warp register pipeline, barrier-free.
// R8/R12: single kernel, in-CTA tensor-core weight fold; aliased epilogue.
// R13: fold prologue made ~5x cheaper (half2-packed transpose staging,
//      f32 direct-gmem bias fold with 4-way ILP, one barrier removed);
//      mainloop ldmatrix batched in groups of 4.
// ============================================================================

#define EMBED 64
#define TILE_M 128
#define STRIDE 72   // halves per smem row of M (144B: conflict-free ldmatrix)
#define NCTA 304    // 2 per SM on GB300 (152 SMs)

typedef unsigned long long u64;

__device__ __forceinline__ int permP(int l) {
    return (l & 48) | ((l & 6) << 1) | ((l & 8) >> 2) | (l & 1);
}
// P is a 3-cycle on bits {1,2,3}: P^-1 = P^2
__device__ __forceinline__ int permPinv(int l) { return permP(permP(l)); }

// ---------------- smem offsets (dynamic, bytes) ------------------------------
static constexpr int SM_M0 = 0;          // M0: 64 x 72 halves = 9216 B
static constexpr int SM_M1 = 9216;
static constexpr int SM_A0 = 18432;      // Wo_P staging (fp16, 64x72)
static constexpr int SM_A1 = 27648;
static constexpr int SM_B0 = 36864;      // Wv_P^T staging (fp16, 64x72)
static constexpr int SM_B1 = 46080;
static constexpr int SM_CB = 55296;      // float[2][64]
static constexpr int SM_GM = 55808;      // float[2][64]
static constexpr int SM_BT = 56320;      // float[2][64]
static constexpr int SM_TOTAL = 56832;

// ---------------- asm helpers ------------------------------------------------
__device__ __forceinline__ void mma16816(float* d, const uint32_t* a, const uint32_t* b) {
    asm volatile(
        "mma.sync.aligned.m16n8k16.row.col.f32.f16.f16.f32 "
        "{%0,%1,%2,%3}, {%4,%5,%6,%7}, {%8,%9}, {%0,%1,%2,%3};"
        : "+f"(d[0]), "+f"(d[1]), "+f"(d[2]), "+f"(d[3])
        : "r"(a[0]), "r"(a[1]), "r"(a[2]), "r"(a[3]), "r"(b[0]), "r"(b[1]));
}
__device__ __forceinline__ float4 ldcs_f4(const float* p) {
    float4 r;
    asm volatile("ld.global.cs.v4.f32 {%0,%1,%2,%3}, [%4];"
                 : "=f"(r.x), "=f"(r.y), "=f"(r.z), "=f"(r.w) : "l"(p));
    return r;
}
__device__ __forceinline__ void stcs_2x64(float* p, u64 a, u64 b) {
    asm volatile("st.global.cs.v2.b64 [%0], {%1,%2};"
                 :: "l"(p), "l"(a), "l"(b) : "memory");
}
__device__ __forceinline__ uint32_t smem_u32(const void* p) {
    uint32_t a;
    asm("{ .reg .u64 t; cvta.to.shared.u64 t, %1; cvt.u32.u64 %0, t; }"
        : "=r"(a) : "l"(p));
    return a;
}
__device__ __forceinline__ void ldmatrix_x4(uint32_t* b, uint32_t addr) {
    asm volatile("ldmatrix.sync.aligned.m8n8.x4.shared.b16 {%0,%1,%2,%3}, [%4];"
                 : "=r"(b[0]), "=r"(b[1]), "=r"(b[2]), "=r"(b[3]) : "r"(addr));
}
__device__ __forceinline__ uint32_t packh2(float a, float b) {
    __half2 h = __floats2half2_rn(a, b);
    return *reinterpret_cast<uint32_t*>(&h);
}
// ---- f32x2 packed math (Blackwell FFMA2; sm_100+ plain PTX) ----
__device__ __forceinline__ u64 pk2(float lo, float hi) {
    u64 r; asm("mov.b64 %0, {%1,%2};" : "=l"(r) : "f"(lo), "f"(hi)); return r;
}
__device__ __forceinline__ void upk2(u64 v, float& lo, float& hi) {
    asm("mov.b64 {%0,%1}, %2;" : "=f"(lo), "=f"(hi) : "l"(v));
}
__device__ __forceinline__ u64 add2(u64 a, u64 b) {
    u64 r; asm("add.rn.f32x2 %0, %1, %2;" : "=l"(r) : "l"(a), "l"(b)); return r;
}
__device__ __forceinline__ u64 mul2(u64 a, u64 b) {
    u64 r; asm("mul.rn.f32x2 %0, %1, %2;" : "=l"(r) : "l"(a), "l"(b)); return r;
}
__device__ __forceinline__ u64 fma2(u64 a, u64 b, u64 c) {
    u64 r; asm("fma.rn.f32x2 %0, %1, %2, %3;" : "=l"(r) : "l"(a), "l"(b), "l"(c)); return r;
}
__device__ __forceinline__ u64 h2tof2(uint32_t h) {
    float2 f = __half22float2(*reinterpret_cast<__half2*>(&h));
    return pk2(f.x, f.y);
}

// issue 8 LDG.128 for one tensor's warp-rows of a tile (no wait)
__device__ __forceinline__ void issue_tile(const float* base, float4* q) {
#pragma unroll
    for (int kt = 0; kt < 4; kt++) {
        q[2 * kt]     = ldcs_f4(base + kt * 16);
        q[2 * kt + 1] = ldcs_f4(base + 8 * EMBED + kt * 16);
    }
}
__device__ __forceinline__ void pack_tile(const float4* q, uint32_t h[4][4]) {
#pragma unroll
    for (int kt = 0; kt < 4; kt++) {
        float4 f0 = q[2 * kt], f1 = q[2 * kt + 1];
        h[kt][0] = packh2(f0.x, f0.y);
        h[kt][1] = packh2(f1.x, f1.y);
        h[kt][2] = packh2(f0.z, f0.w);
        h[kt][3] = packh2(f1.z, f1.w);
    }
}

// one output: GEMM(A) + bias + residual(R) + LayerNorm + store.
// e overwrites acc in place; ldmatrix batched in groups of 4.
__device__ __forceinline__ void compute_store(
    const uint32_t Ah[4][4], const uint32_t Rh[4][4],
    uint32_t smM, uint32_t lmoff,
    const u64* cb2, const u64* gm2, const u64* bt2,
    int tq, float* __restrict__ outp) {
    float acc[8][4];
#pragma unroll
    for (int nt = 0; nt < 8; nt++)
#pragma unroll
        for (int q = 0; q < 4; q++) acc[nt][q] = 0.f;

#pragma unroll
    for (int ktp = 0; ktp < 2; ktp++) {
#pragma unroll
        for (int ng = 0; ng < 2; ng++) {
            uint32_t b[4][4];
#pragma unroll
            for (int j = 0; j < 4; j++)
                ldmatrix_x4(b[j], smM + lmoff +
                            (uint32_t)((ng * 4 + j) * 8 * STRIDE * 2 + ktp * 64));
#pragma unroll
            for (int j = 0; j < 4; j++) {
                mma16816(acc[ng * 4 + j], Ah[2 * ktp], b[j]);
                mma16816(acc[ng * 4 + j], Ah[2 * ktp + 1], b[j] + 2);
            }
        }
    }

    // --- packed epilogue: acc <- acc + bias + residual; accumulate s, ss ---
    u64 sp0 = 0ULL, ssp0 = 0ULL, sp1 = 0ULL, ssp1 = 0ULL;
#pragma unroll
    for (int kt = 0; kt < 4; kt++) {
        u64 cA = cb2[kt * 8 + tq * 2];
        u64 cB = cb2[kt * 8 + tq * 2 + 1];
        u64 eA0 = add2(pk2(acc[2 * kt][0], acc[2 * kt][1]),
                       add2(cA, h2tof2(Rh[kt][0])));
        u64 eB0 = add2(pk2(acc[2 * kt + 1][0], acc[2 * kt + 1][1]),
                       add2(cB, h2tof2(Rh[kt][2])));
        u64 eA1 = add2(pk2(acc[2 * kt][2], acc[2 * kt][3]),
                       add2(cA, h2tof2(Rh[kt][1])));
        u64 eB1 = add2(pk2(acc[2 * kt + 1][2], acc[2 * kt + 1][3]),
                       add2(cB, h2tof2(Rh[kt][3])));
        upk2(eA0, acc[2 * kt][0], acc[2 * kt][1]);
        upk2(eB0, acc[2 * kt + 1][0], acc[2 * kt + 1][1]);
        upk2(eA1, acc[2 * kt][2], acc[2 * kt][3]);
        upk2(eB1, acc[2 * kt + 1][2], acc[2 * kt + 1][3]);
        sp0 = add2(sp0, eA0); sp0 = add2(sp0, eB0);
        sp1 = add2(sp1, eA1); sp1 = add2(sp1, eB1);
        ssp0 = fma2(eA0, eA0, ssp0); ssp0 = fma2(eB0, eB0, ssp0);
        ssp1 = fma2(eA1, eA1, ssp1); ssp1 = fma2(eB1, eB1, ssp1);
    }
    float s0, ss0, s1, ss1, ta, tb;
    upk2(sp0, ta, tb);  s0 = ta + tb;
    upk2(ssp0, ta, tb); ss0 = ta + tb;
    upk2(sp1, ta, tb);  s1 = ta + tb;
    upk2(ssp1, ta, tb); ss1 = ta + tb;
    s0  += __shfl_xor_sync(0xFFFFFFFFu, s0, 1);
    s0  += __shfl_xor_sync(0xFFFFFFFFu, s0, 2);
    ss0 += __shfl_xor_sync(0xFFFFFFFFu, ss0, 1);
    ss0 += __shfl_xor_sync(0xFFFFFFFFu, ss0, 2);
    s1  += __shfl_xor_sync(0xFFFFFFFFu, s1, 1);
    s1  += __shfl_xor_sync(0xFFFFFFFFu, s1, 2);
    ss1 += __shfl_xor_sync(0xFFFFFFFFu, ss1, 1);
    ss1 += __shfl_xor_sync(0xFFFFFFFFu, ss1, 2);
    float mu0 = s0 * (1.f / 64.f);
    float mu1 = s1 * (1.f / 64.f);
    float rs0 = rsqrtf(ss0 * (1.f / 64.f) - mu0 * mu0 + 1e-5f);
    float rs1 = rsqrtf(ss1 * (1.f / 64.f) - mu1 * mu1 + 1e-5f);

    const u64 nmu0 = pk2(-mu0, -mu0), rs0p = pk2(rs0, rs0);
    const u64 nmu1 = pk2(-mu1, -mu1), rs1p = pk2(rs1, rs1);
#pragma unroll
    for (int kt = 0; kt < 4; kt++) {
        u64 G0 = gm2[kt * 8 + tq * 2], G1 = gm2[kt * 8 + tq * 2 + 1];
        u64 T0 = bt2[kt * 8 + tq * 2], T1 = bt2[kt * 8 + tq * 2 + 1];
        u64 rg00 = mul2(rs0p, G0), rg01 = mul2(rs0p, G1);
        u64 rg10 = mul2(rs1p, G0), rg11 = mul2(rs1p, G1);
        u64 y00 = fma2(add2(pk2(acc[2 * kt][0], acc[2 * kt][1]), nmu0), rg00, T0);
        u64 y01 = fma2(add2(pk2(acc[2 * kt + 1][0], acc[2 * kt + 1][1]), nmu0), rg01, T1);
        u64 y10 = fma2(add2(pk2(acc[2 * kt][2], acc[2 * kt][3]), nmu1), rg10, T0);
        u64 y11 = fma2(add2(pk2(acc[2 * kt + 1][2], acc[2 * kt + 1][3]), nmu1), rg11, T1);
        stcs_2x64(outp + kt * 16, y00, y01);
        stcs_2x64(outp + 8 * EMBED + kt * 16, y10, y11);
    }
}

__global__ void __launch_bounds__(256, 2)
fused_kernel(const float* __restrict__ v1, const float* __restrict__ v2,
             const float* __restrict__ Wo1, const float* __restrict__ Wv2,
             const float* __restrict__ bv2, const float* __restrict__ bo1,
             const float* __restrict__ Wo2, const float* __restrict__ Wv1,
             const float* __restrict__ bv1, const float* __restrict__ bo2,
             const float* __restrict__ g1, const float* __restrict__ be1,
             const float* __restrict__ g2, const float* __restrict__ be2,
             float* __restrict__ out, int Btot) {
    extern __shared__ char smem[];
    const int tid = threadIdx.x;
    const int wid = tid >> 5, lane = tid & 31;
    const int g = lane >> 2, tq = lane & 3;
    const int wrow = wid * 16;
    const int ntiles = Btot / TILE_M;

    // ===================== in-CTA weight fold (once) =========================
    // (1) stage Wo_P (half2 rows) and Wv_P^T (half2-packed transpose pairs)
#pragma unroll
    for (int m = 0; m < 2; m++) {
        const float* Wo = m ? Wo2 : Wo1;
        const float* Wv = m ? Wv1 : Wv2;
        char* sA = smem + (m ? SM_A1 : SM_A0);
        char* sB = smem + (m ? SM_B1 : SM_B0);
        for (int idx = tid; idx < 2048; idx += 256) {
            int r = idx >> 5, c2 = (idx & 31) * 2;
            float2 wo = *(const float2*)(Wo + r * 64 + c2);
            *(__half2*)(sA + permPinv(r) * 144 + c2 * 2) =
                __floats2half2_rn(wo.x, wo.y);
        }
        for (int idx = tid; idx < 1024; idx += 256) {
            int r2 = idx >> 5;          // i-pair index 0..31 (i = 2*r2, 2*r2+1)
            int c2 = (idx & 31) * 2;    // k column pair
            float2 wa = *(const float2*)(Wv + (2 * r2) * 64 + c2);
            float2 wb = *(const float2*)(Wv + (2 * r2 + 1) * 64 + c2);
            *(__half2*)(sB + permPinv(c2) * 144 + r2 * 4) =
                __floats2half2_rn(wa.x, wb.x);
            *(__half2*)(sB + permPinv(c2 + 1) * 144 + r2 * 4) =
                __floats2half2_rn(wa.y, wb.y);
        }
    }
    // (2) bias fold: direct coalesced f32 gmem reads, 4 independent chains
    if (tid < 128) {
        const int m = tid >> 6, tt = tid & 63;
        const float* Wo = m ? Wo2 : Wo1;
        const float* bv = m ? bv1 : bv2;
        const float* bo = m ? bo2 : bo1;
        float a0 = bo[tt], a1 = 0.f, a2 = 0.f, a3 = 0.f;
#pragma unroll 4
        for (int i = 0; i < 64; i += 4) {
            float4 w = *(const float4*)(Wo + tt * 64 + i);
            float4 b = *(const float4*)(bv + i);
            a0 = fmaf(w.x, b.x, a0);
            a1 = fmaf(w.y, b.y, a1);
            a2 = fmaf(w.z, b.z, a2);
            a3 = fmaf(w.w, b.w, a3);
        }
        ((float*)(smem + SM_CB))[m * 64 + tt] = (a0 + a1) + (a2 + a3);
    }
    // (3) LN constants
    if (tid < 64) {
        ((float*)(smem + SM_GM))[tid]      = g1[tid];
        ((float*)(smem + SM_GM))[64 + tid] = g2[tid];
        ((float*)(smem + SM_BT))[tid]      = be1[tid];
        ((float*)(smem + SM_BT))[64 + tid] = be2[tid];
    }
    __syncthreads();

    // (4) tensor-core fold: warps 0-3 -> M0, warps 4-7 -> M1, 16 rows each
    {
        const int m = wid >> 2;
        const int j0 = (wid & 3) * 16;
        const uint32_t sA = smem_u32(smem + (m ? SM_A1 : SM_A0)) + (uint32_t)(j0 * 144);
        const uint32_t sB = smem_u32(smem + (m ? SM_B1 : SM_B0));
        char* sM = smem + (m ? SM_M1 : SM_M0);
        const uint32_t almoff = (uint32_t)((lane & 7) * 144 +
                                           ((lane >> 3) & 1) * (8 * 144) +
                                           ((lane >> 4) & 1) * 16);
        const uint32_t blmoff = (uint32_t)((lane & 7) * 144 +
                                           ((lane >> 4) & 1) * 32 +
                                           ((lane >> 3) & 1) * 16);
        float acc[8][4];
#pragma unroll
        for (int nt = 0; nt < 8; nt++)
#pragma unroll
            for (int q = 0; q < 4; q++) acc[nt][q] = 0.f;
#pragma unroll
        for (int ktp = 0; ktp < 2; ktp++) {
            uint32_t aF0[4], aF1[4];
            ldmatrix_x4(aF0, sA + almoff + (uint32_t)(ktp * 64));
            ldmatrix_x4(aF1, sA + almoff + (uint32_t)(ktp * 64 + 32));
#pragma unroll
            for (int nt = 0; nt < 8; nt++) {
                uint32_t b[4];
                ldmatrix_x4(b, sB + blmoff + (uint32_t)(nt * 8 * 144 + ktp * 64));
                mma16816(acc[nt], aF0, b);
                mma16816(acc[nt], aF1, b + 2);
            }
        }
#pragma unroll
        for (int nt = 0; nt < 8; nt++) {
            int col = (8 * nt + 2 * tq) * 2;
            *(__half2*)(sM + (j0 + g) * 144 + col) =
                __floats2half2_rn(acc[nt][0], acc[nt][1]);
            *(__half2*)(sM + (j0 + g + 8) * 144 + col) =
                __floats2half2_rn(acc[nt][2], acc[nt][3]);
        }
    }
    __syncthreads();  // fold complete; mainloop below is barrier-free

    // ===================== persistent pipelined mainloop =====================
    const uint32_t smM0 = smem_u32(smem + SM_M0);
    const uint32_t smM1 = smem_u32(smem + SM_M1);
    const uint32_t lmoff = (uint32_t)((lane & 7) * (STRIDE * 2) +
                                      ((lane >> 4) & 1) * 32 +
                                      ((lane >> 3) & 1) * 16);
    const u64* cb0 = (const u64*)(smem + SM_CB);
    const u64* cb1 = cb0 + 32;
    const u64* gm0 = (const u64*)(smem + SM_GM);
    const u64* gm1 = gm0 + 32;
    const u64* bt0 = (const u64*)(smem + SM_BT);
    const u64* bt1 = bt0 + 32;

    const int lrow = wrow + g;
    const size_t lcol = (size_t)tq * 4;
    const size_t o2off = (size_t)Btot * EMBED;

    int tile = blockIdx.x;
    if (tile >= ntiles) return;

    uint32_t cur1[4][4], cur2[4][4];
    {
        float4 q[16];
        const size_t base = ((size_t)tile * TILE_M + lrow) * EMBED + lcol;
        issue_tile(v1 + base, q);
        issue_tile(v2 + base, q + 8);
        pack_tile(q, cur1);
        pack_tile(q + 8, cur2);
    }

    for (;;) {
        const int next = tile + NCTA;
        const bool has_next = next < ntiles;
        const size_t nbase = ((size_t)(has_next ? next : tile) * TILE_M + lrow) * EMBED + lcol;
        const size_t obase = ((size_t)tile * TILE_M + lrow) * EMBED + lcol;

        // prefetch v2(next) while computing output 1 of current tile
        float4 qa[8];
        issue_tile(v2 + nbase, qa);
        compute_store(cur2, cur1, smM0, lmoff, cb0, gm0, bt0, tq, out + obase);
        uint32_t nv2[4][4];
        pack_tile(qa, nv2);

        // prefetch v1(next) while computing output 2 of current tile
        float4 qb[8];
        issue_tile(v1 + nbase, qb);
        compute_store(cur1, cur2, smM1, lmoff, cb1, gm1, bt1, tq, out + o2off + obase);

        if (!has_next) break;
        pack_tile(qb, cur1);
#pragma unroll
        for (int kt = 0; kt < 4; kt++)
#pragma unroll
            for (int s = 0; s < 4; s++) cur2[kt][s] = nv2[kt][s];
        tile = next;
    }
}

// ---------------- launcher ---------------------------------------------------
extern "C" void kernel_launch(void* const* d_in, const int* in_sizes, int n_in,
                              void* d_out, int out_size) {
    // 0 v1, 1 v2, 2 Wq1, 3 bq1, 4 Wk2, 5 bk2, 6 Wv2, 7 bv2, 8 Wo1, 9 bo1,
    // 10 Wq2, 11 bq2, 12 Wk1, 13 bk1, 14 Wv1, 15 bv1, 16 Wo2, 17 bo2,
    // 18 g1, 19 be1, 20 g2, 21 be2
    const float* v1  = (const float*)d_in[0];
    const float* v2  = (const float*)d_in[1];
    const float* Wv2 = (const float*)d_in[6];
    const float* bv2 = (const float*)d_in[7];
    const float* Wo1 = (const float*)d_in[8];
    const float* bo1 = (const float*)d_in[9];
    const float* Wv1 = (const float*)d_in[14];
    const float* bv1 = (const float*)d_in[15];
    const float* Wo2 = (const float*)d_in[16];
    const float* bo2 = (const float*)d_in[17];
    const float* g1  = (const float*)d_in[18];
    const float* be1 = (const float*)d_in[19];
    const float* g2  = (const float*)d_in[20];
    const float* be2 = (const float*)d_in[21];
    float* out = (float*)d_out;

    int Btot = in_sizes[0] / EMBED;

    static bool attr_set = false;
    if (!attr_set) {
        cudaFuncSetAttribute(fused_kernel,
                             cudaFuncAttributeMaxDynamicSharedMemorySize, SM_TOTAL);
        attr_set = true;
    }
    fused_kernel<<<NCTA, 256, SM_TOTAL>>>(v1, v2, Wo1, Wv2, bv2, bo1,
                                          Wo2, Wv1, bv1, bo2,
                                          g1, be1, g2, be2, out, Btot);
}